// round 2
// baseline (speedup 1.0000x reference)
#include <cuda_runtime.h>

// Edge_27547920236817: B=16, C=3, H=W=512 f32 in; out (B, C*8, H, W) f32.
// Reference facts exploited:
//  - All accesses in the valid (cropped) region hit real image data (no pad, no wrap).
//  - rl() rolls (channel, H): a-shift -> channel (c-a)%3, b-shift -> row y-b.
//  - Output rows/cols 0,1,510,511 are zero (MARG=2).

#define HH 512
#define WW 512
#define PLANE (HH * WW)   // 1<<18

__device__ __forceinline__ float sg(float t) {
    // sigmoid(10*t) — EX2 + RCP (MUFU), ~1 ulp class accuracy
    return __fdividef(1.0f, 1.0f + __expf(-10.0f * t));
}

__global__ void __launch_bounds__(256) edge_kernel(const float* __restrict__ in,
                                                   float* __restrict__ out) {
    int idx = blockIdx.x * blockDim.x + threadIdx.x;   // 16*3*512*512 threads
    int x  = idx & (WW - 1);
    int y  = (idx >> 9) & (HH - 1);
    int bc = idx >> 18;          // b*3 + c
    int c  = bc - (bc / 3) * 3;
    int b  = bc / 3;

    // output base: (b*24 + c*8 + k) planes
    float* o = out + (((b * 24 + c * 8) << 18) + (y << 9) + x);

    if (x < 2 || x >= WW - 2 || y < 2 || y >= HH - 2) {
        #pragma unroll
        for (int k = 0; k < 8; k++) o[k << 18] = 0.0f;
        return;
    }

    int cm = (c + 2) % 3;   // rl a=+1 -> channel (c-1)%3
    int cp = (c + 1) % 3;   // rl a=-1 -> channel (c+1)%3

    const float* p  = in + (bc << 18);
    const float* pa = in + ((b * 3 + cm) << 18);
    const float* pc = in + ((b * 3 + cp) << 18);

    int r  = (y << 9) + x;      // row y
    int rm1 = r - WW, rp1 = r + WW, rm2 = r - 2 * WW;

    // own-channel neighborhood
    float v00   = __ldg(p + r);
    float vm1m1 = __ldg(p + rm1 - 1);
    float vm10  = __ldg(p + rm1);
    float vm1p1 = __ldg(p + rm1 + 1);
    float v0m1  = __ldg(p + r - 1);
    float v0p1  = __ldg(p + r + 1);
    float vp1m1 = __ldg(p + rp1 - 1);
    float vp10  = __ldg(p + rp1);
    float vp1p1 = __ldg(p + rp1 + 1);
    float vm20  = __ldg(p + rm2);

    // channel cm ( = (c-1) mod 3 )
    float a00   = __ldg(pa + r);
    float a0m1  = __ldg(pa + r - 1);
    float a0p1  = __ldg(pa + r + 1);
    float am10  = __ldg(pa + rm1);
    float am2p1 = __ldg(pa + rm2 + 1);
    float am2m1 = __ldg(pa + rm2 - 1);

    // channel cp ( = (c+1) mod 3 )
    float cm10  = __ldg(pc + rm1);
    float cm2m1 = __ldg(pc + rm2 - 1);
    float c0m1  = __ldg(pc + r - 1);

    // own-channel diffs at (y,x): diff_s = X(y-s0, x-s1) - X(y,x)
    float d10   = vm10  - v00;   // (1,0)
    float dn10  = vp10  - v00;   // (-1,0)
    float d01   = v0m1  - v00;   // (0,1)
    float dn01  = v0p1  - v00;   // (0,-1)
    float d11   = vm1m1 - v00;   // (1,1)
    float dnn11 = vp1p1 - v00;   // (-1,-1)
    float dn11  = vp1m1 - v00;   // (-1,1)
    float d1n1  = vm1p1 - v00;   // (1,-1)

    // rl(.,(1,0)) at (c,y,x) = diff at (cm, y, x)
    float rd01_a  = a0m1 - a00;
    float rdn01_a = a0p1 - a00;

    // rl(.,(0,1)) = diff at (c, y-1, x)
    float rd10_u  = vm20  - vm10;
    float rdn10_u = v00   - vm10;
    float rd01_u  = vm1m1 - vm10;

    // rl(.,(1,1)) = diff at (cm, y-1, x)
    float rdn11_b = a0m1  - am10;
    float rd1n1_b = am2p1 - am10;
    float rd11_b  = am2m1 - am10;

    // rl(.,(-1,1)) = diff at (cp, y-1, x)
    float rd11_c  = cm2m1 - cm10;
    float rdn11_c = c0m1  - cm10;

    // ---- group 10 ----
    float ad10r = fabsf(d10);
    float gate10 = sg(ad10r);
    float ad10 = ad10r * gate10;
    float e10 = sg(ad10 - fabsf(d01)) + sg(ad10 - fabsf(dn01)) + sg(ad10 - fabsf(dn10))
              + 2.0f * sg(ad10 - fabsf(rd01_a)) + sg(ad10 - fabsf(rdn01_a));
    float g10 = sg(e10 - 4.0f);
    float s10 = sg(d10);
    float o0 = g10 * s10;
    float o1 = g10 * (1.0f - s10);

    // ---- group 01 (note: gated by MODIFIED ad10; e01n == e01 per reference) ----
    float ad01 = fabsf(d01) * sg(ad10);
    float e01 = sg(ad01 - fabsf(d10)) + sg(ad01 - fabsf(dn10)) + sg(ad01 - fabsf(dn01))
              + sg(ad01 - fabsf(rd10_u)) + sg(ad01 - fabsf(rdn10_u)) + sg(ad01 - fabsf(rd01_u));
    float g01 = sg(e01 - 4.0f);
    float s01 = sg(d01);
    float o2 = g01 * s01;
    float o3 = g01 * s01;   // reference quirk: same as o2

    // ---- group 11 ----
    float ad11r = fabsf(d11);
    float ad11 = ad11r * sg(ad11r);
    float e11 = sg(ad11 - fabsf(dn11)) + sg(ad11 - fabsf(d1n1)) + sg(ad11 - fabsf(dnn11))
              + sg(ad11 - fabsf(rdn11_b)) + sg(ad11 - fabsf(rd1n1_b)) + sg(ad11 - fabsf(rd11_b));
    float g11 = sg(e11 - 4.0f);
    float s11 = sg(d11);
    float o4 = g11 * s11;
    float o5 = g11 * (1.0f - s11);

    // ---- group n11 (hard gate (ad>0): identity on |.|) ----
    float adn11 = fabsf(dn11);
    float en11 = sg(adn11 - fabsf(d11)) + sg(adn11 - fabsf(d1n1)) + sg(adn11 - fabsf(dnn11))
               + sg(adn11 - fabsf(rd11_c)) + 2.0f * sg(adn11 - fabsf(rdn11_c));
    float gn11 = sg(en11 - 4.0f);
    float sn11 = sg(dn11);
    float o6 = gn11 * sn11;
    float o7 = gn11 * (1.0f - sn11);

    o[0 << 18] = o0;
    o[1 << 18] = o1;
    o[2 << 18] = o2;
    o[3 << 18] = o3;
    o[4 << 18] = o4;
    o[5 << 18] = o5;
    o[6 << 18] = o6;
    o[7 << 18] = o7;
}

extern "C" void kernel_launch(void* const* d_in, const int* in_sizes, int n_in,
                              void* d_out, int out_size) {
    const float* x = (const float*)d_in[0];
    float* out = (float*)d_out;
    int total = 16 * 3 * HH * WW;
    edge_kernel<<<total / 256, 256>>>(x, out);
}

// round 3
// speedup vs baseline: 1.0016x; 1.0016x over previous
#include <cuda_runtime.h>

// Edge_27547920236817: B=16, C=3, H=W=512 f32 in; out (B, C*8, H, W) f32.
// Reference facts exploited:
//  - All accesses in the valid (cropped) region hit real image data (no pad, no wrap).
//  - rl() rolls (channel, H): a-shift -> channel (c-a)%3, b-shift -> row y-b.
//  - Output rows/cols 0,1,510,511 are zero (MARG=2).

#define HH 512
#define WW 512
#define PLANE (HH * WW)   // 1<<18

__device__ __forceinline__ float sg(float t) {
    // sigmoid(10*t) — EX2 + RCP (MUFU), ~1 ulp class accuracy
    return __fdividef(1.0f, 1.0f + __expf(-10.0f * t));
}

__global__ void __launch_bounds__(256) edge_kernel(const float* __restrict__ in,
                                                   float* __restrict__ out) {
    int idx = blockIdx.x * blockDim.x + threadIdx.x;   // 16*3*512*512 threads
    int x  = idx & (WW - 1);
    int y  = (idx >> 9) & (HH - 1);
    int bc = idx >> 18;          // b*3 + c
    int c  = bc - (bc / 3) * 3;
    int b  = bc / 3;

    // output base: (b*24 + c*8 + k) planes
    float* o = out + (((b * 24 + c * 8) << 18) + (y << 9) + x);

    if (x < 2 || x >= WW - 2 || y < 2 || y >= HH - 2) {
        #pragma unroll
        for (int k = 0; k < 8; k++) o[k << 18] = 0.0f;
        return;
    }

    int cm = (c + 2) % 3;   // rl a=+1 -> channel (c-1)%3
    int cp = (c + 1) % 3;   // rl a=-1 -> channel (c+1)%3

    const float* p  = in + (bc << 18);
    const float* pa = in + ((b * 3 + cm) << 18);
    const float* pc = in + ((b * 3 + cp) << 18);

    int r  = (y << 9) + x;      // row y
    int rm1 = r - WW, rp1 = r + WW, rm2 = r - 2 * WW;

    // own-channel neighborhood
    float v00   = __ldg(p + r);
    float vm1m1 = __ldg(p + rm1 - 1);
    float vm10  = __ldg(p + rm1);
    float vm1p1 = __ldg(p + rm1 + 1);
    float v0m1  = __ldg(p + r - 1);
    float v0p1  = __ldg(p + r + 1);
    float vp1m1 = __ldg(p + rp1 - 1);
    float vp10  = __ldg(p + rp1);
    float vp1p1 = __ldg(p + rp1 + 1);
    float vm20  = __ldg(p + rm2);

    // channel cm ( = (c-1) mod 3 )
    float a00   = __ldg(pa + r);
    float a0m1  = __ldg(pa + r - 1);
    float a0p1  = __ldg(pa + r + 1);
    float am10  = __ldg(pa + rm1);
    float am2p1 = __ldg(pa + rm2 + 1);
    float am2m1 = __ldg(pa + rm2 - 1);

    // channel cp ( = (c+1) mod 3 )
    float cm10  = __ldg(pc + rm1);
    float cm2m1 = __ldg(pc + rm2 - 1);
    float c0m1  = __ldg(pc + r - 1);

    // own-channel diffs at (y,x): diff_s = X(y-s0, x-s1) - X(y,x)
    float d10   = vm10  - v00;   // (1,0)
    float dn10  = vp10  - v00;   // (-1,0)
    float d01   = v0m1  - v00;   // (0,1)
    float dn01  = v0p1  - v00;   // (0,-1)
    float d11   = vm1m1 - v00;   // (1,1)
    float dnn11 = vp1p1 - v00;   // (-1,-1)
    float dn11  = vp1m1 - v00;   // (-1,1)
    float d1n1  = vm1p1 - v00;   // (1,-1)

    // rl(.,(1,0)) at (c,y,x) = diff at (cm, y, x)
    float rd01_a  = a0m1 - a00;
    float rdn01_a = a0p1 - a00;

    // rl(.,(0,1)) = diff at (c, y-1, x)
    float rd10_u  = vm20  - vm10;
    float rdn10_u = v00   - vm10;
    float rd01_u  = vm1m1 - vm10;

    // rl(.,(1,1)) = diff at (cm, y-1, x)
    float rdn11_b = a0m1  - am10;
    float rd1n1_b = am2p1 - am10;
    float rd11_b  = am2m1 - am10;

    // rl(.,(-1,1)) = diff at (cp, y-1, x)
    float rd11_c  = cm2m1 - cm10;
    float rdn11_c = c0m1  - cm10;

    // ---- group 10 ----
    float ad10r = fabsf(d10);
    float gate10 = sg(ad10r);
    float ad10 = ad10r * gate10;
    float e10 = sg(ad10 - fabsf(d01)) + sg(ad10 - fabsf(dn01)) + sg(ad10 - fabsf(dn10))
              + 2.0f * sg(ad10 - fabsf(rd01_a)) + sg(ad10 - fabsf(rdn01_a));
    float g10 = sg(e10 - 4.0f);
    float s10 = sg(d10);
    float o0 = g10 * s10;
    float o1 = g10 * (1.0f - s10);

    // ---- group 01 (note: gated by MODIFIED ad10; e01n == e01 per reference) ----
    float ad01 = fabsf(d01) * sg(ad10);
    float e01 = sg(ad01 - fabsf(d10)) + sg(ad01 - fabsf(dn10)) + sg(ad01 - fabsf(dn01))
              + sg(ad01 - fabsf(rd10_u)) + sg(ad01 - fabsf(rdn10_u)) + sg(ad01 - fabsf(rd01_u));
    float g01 = sg(e01 - 4.0f);
    float s01 = sg(d01);
    float o2 = g01 * s01;
    float o3 = g01 * s01;   // reference quirk: same as o2

    // ---- group 11 ----
    float ad11r = fabsf(d11);
    float ad11 = ad11r * sg(ad11r);
    float e11 = sg(ad11 - fabsf(dn11)) + sg(ad11 - fabsf(d1n1)) + sg(ad11 - fabsf(dnn11))
              + sg(ad11 - fabsf(rdn11_b)) + sg(ad11 - fabsf(rd1n1_b)) + sg(ad11 - fabsf(rd11_b));
    float g11 = sg(e11 - 4.0f);
    float s11 = sg(d11);
    float o4 = g11 * s11;
    float o5 = g11 * (1.0f - s11);

    // ---- group n11 (hard gate (ad>0): identity on |.|) ----
    float adn11 = fabsf(dn11);
    float en11 = sg(adn11 - fabsf(d11)) + sg(adn11 - fabsf(d1n1)) + sg(adn11 - fabsf(dnn11))
               + sg(adn11 - fabsf(rd11_c)) + 2.0f * sg(adn11 - fabsf(rdn11_c));
    float gn11 = sg(en11 - 4.0f);
    float sn11 = sg(dn11);
    float o6 = gn11 * sn11;
    float o7 = gn11 * (1.0f - sn11);

    o[0 << 18] = o0;
    o[1 << 18] = o1;
    o[2 << 18] = o2;
    o[3 << 18] = o3;
    o[4 << 18] = o4;
    o[5 << 18] = o5;
    o[6 << 18] = o6;
    o[7 << 18] = o7;
}

extern "C" void kernel_launch(void* const* d_in, const int* in_sizes, int n_in,
                              void* d_out, int out_size) {
    const float* x = (const float*)d_in[0];
    float* out = (float*)d_out;
    int total = 16 * 3 * HH * WW;
    edge_kernel<<<total / 256, 256>>>(x, out);
}

// round 4
// speedup vs baseline: 1.6001x; 1.5975x over previous
#include <cuda_runtime.h>

// Edge_27547920236817: B=16, C=3, H=W=512 f32 in; out (B, C*8, H, W) f32.
// R3: sigmoid(10t) = 0.5 + 0.5*tanh(5t) via MUFU.TANH (1 MUFU vs EX2+RCP),
//     inputs pre-scaled by 5 so every tanh arg is natively scaled,
//     e-sums carried as raw tanh sums: 5*(e-4) = 2.5*T - 5.

#define HH 512
#define WW 512

__device__ __forceinline__ float th(float x) {
    float y;
    asm("tanh.approx.f32 %0, %1;" : "=f"(y) : "f"(x));
    return y;
}

__global__ void __launch_bounds__(256) edge_kernel(const float* __restrict__ in,
                                                   float* __restrict__ out) {
    int idx = blockIdx.x * blockDim.x + threadIdx.x;
    int x  = idx & (WW - 1);
    int y  = (idx >> 9) & (HH - 1);
    int bc = idx >> 18;          // b*3 + c
    int c  = bc - (bc / 3) * 3;
    int b  = bc / 3;

    float* o = out + (((b * 24 + c * 8) << 18) + (y << 9) + x);

    if (x < 2 || x >= WW - 2 || y < 2 || y >= HH - 2) {
        #pragma unroll
        for (int k = 0; k < 8; k++) o[k << 18] = 0.0f;
        return;
    }

    int cm = (c + 2) % 3;   // rl a=+1 -> channel (c-1)%3
    int cp = (c + 1) % 3;   // rl a=-1 -> channel (c+1)%3

    const float* p  = in + (bc << 18);
    const float* pa = in + ((b * 3 + cm) << 18);
    const float* pc = in + ((b * 3 + cp) << 18);

    int r   = (y << 9) + x;
    int rm1 = r - WW, rp1 = r + WW, rm2 = r - 2 * WW;

    const float S = 5.0f;   // pre-scale: tanh arg units

    // own-channel neighborhood (scaled by 5)
    float v00   = S * __ldg(p + r);
    float vm1m1 = S * __ldg(p + rm1 - 1);
    float vm10  = S * __ldg(p + rm1);
    float vm1p1 = S * __ldg(p + rm1 + 1);
    float v0m1  = S * __ldg(p + r - 1);
    float v0p1  = S * __ldg(p + r + 1);
    float vp1m1 = S * __ldg(p + rp1 - 1);
    float vp10  = S * __ldg(p + rp1);
    float vp1p1 = S * __ldg(p + rp1 + 1);
    float vm20  = S * __ldg(p + rm2);

    // channel cm
    float a00   = S * __ldg(pa + r);
    float a0m1  = S * __ldg(pa + r - 1);
    float a0p1  = S * __ldg(pa + r + 1);
    float am10  = S * __ldg(pa + rm1);
    float am2p1 = S * __ldg(pa + rm2 + 1);
    float am2m1 = S * __ldg(pa + rm2 - 1);

    // channel cp
    float cm10  = S * __ldg(pc + rm1);
    float cm2m1 = S * __ldg(pc + rm2 - 1);
    float c0m1  = S * __ldg(pc + r - 1);

    // scaled diffs
    float d10   = vm10  - v00;
    float dn10  = vp10  - v00;
    float d01   = v0m1  - v00;
    float dn01  = v0p1  - v00;
    float d11   = vm1m1 - v00;
    float dnn11 = vp1p1 - v00;
    float dn11  = vp1m1 - v00;
    float d1n1  = vm1p1 - v00;

    float rd01_a  = a0m1 - a00;      // rl(.,(1,0))
    float rdn01_a = a0p1 - a00;
    float rd10_u  = vm20  - vm10;    // rl(.,(0,1))
    float rdn10_u = v00   - vm10;
    float rd01_u  = vm1m1 - vm10;
    float rdn11_b = a0m1  - am10;    // rl(.,(1,1))
    float rd1n1_b = am2p1 - am10;
    float rd11_b  = am2m1 - am10;
    float rd11_c  = cm2m1 - cm10;    // rl(.,(-1,1))
    float rdn11_c = c0m1  - cm10;

    // ---- group 10 ----
    float ad10r = fabsf(d10);
    float gate10 = fmaf(0.5f, th(ad10r), 0.5f);
    float ad10 = ad10r * gate10;
    float T10 = th(ad10 - fabsf(d01)) + th(ad10 - fabsf(dn01)) + th(ad10 - fabsf(dn10))
              + 2.0f * th(ad10 - fabsf(rd01_a)) + th(ad10 - fabsf(rdn01_a));
    float g10 = fmaf(0.5f, th(fmaf(2.5f, T10, -5.0f)), 0.5f);
    float s10 = fmaf(0.5f, th(d10), 0.5f);
    float o0 = g10 * s10;
    float o1 = g10 - o0;

    // ---- group 01 (gated by MODIFIED ad10; e01n == e01 per reference) ----
    float ad01 = fabsf(d01) * fmaf(0.5f, th(ad10), 0.5f);
    float T01 = th(ad01 - fabsf(d10)) + th(ad01 - fabsf(dn10)) + th(ad01 - fabsf(dn01))
              + th(ad01 - fabsf(rd10_u)) + th(ad01 - fabsf(rdn10_u)) + th(ad01 - fabsf(rd01_u));
    float g01 = fmaf(0.5f, th(fmaf(2.5f, T01, -5.0f)), 0.5f);
    float s01 = fmaf(0.5f, th(d01), 0.5f);
    float o2 = g01 * s01;
    float o3 = o2;   // reference quirk

    // ---- group 11 ----
    float ad11r = fabsf(d11);
    float ad11 = ad11r * fmaf(0.5f, th(ad11r), 0.5f);
    float T11 = th(ad11 - fabsf(dn11)) + th(ad11 - fabsf(d1n1)) + th(ad11 - fabsf(dnn11))
              + th(ad11 - fabsf(rdn11_b)) + th(ad11 - fabsf(rd1n1_b)) + th(ad11 - fabsf(rd11_b));
    float g11 = fmaf(0.5f, th(fmaf(2.5f, T11, -5.0f)), 0.5f);
    float s11 = fmaf(0.5f, th(d11), 0.5f);
    float o4 = g11 * s11;
    float o5 = g11 - o4;

    // ---- group n11 (hard gate (ad>0) is identity on |.|) ----
    float adn11 = fabsf(dn11);
    float Tn11 = th(adn11 - fabsf(d11)) + th(adn11 - fabsf(d1n1)) + th(adn11 - fabsf(dnn11))
               + th(adn11 - fabsf(rd11_c)) + 2.0f * th(adn11 - fabsf(rdn11_c));
    float gn11 = fmaf(0.5f, th(fmaf(2.5f, Tn11, -5.0f)), 0.5f);
    float sn11 = fmaf(0.5f, th(dn11), 0.5f);
    float o6 = gn11 * sn11;
    float o7 = gn11 - o6;

    o[0 << 18] = o0;
    o[1 << 18] = o1;
    o[2 << 18] = o2;
    o[3 << 18] = o3;
    o[4 << 18] = o4;
    o[5 << 18] = o5;
    o[6 << 18] = o6;
    o[7 << 18] = o7;
}

extern "C" void kernel_launch(void* const* d_in, const int* in_sizes, int n_in,
                              void* d_out, int out_size) {
    const float* x = (const float*)d_in[0];
    float* out = (float*)d_out;
    int total = 16 * 3 * HH * WW;
    edge_kernel<<<total / 256, 256>>>(x, out);
}